// round 1
// baseline (speedup 1.0000x reference)
#include <cuda_runtime.h>

// Problem constants (fixed by dataset): B=1024, S=40*40=1600, V=32
#define SEQL  1600
#define VOC   32
#define GRIDW 40
#define NW    50          // 1600 bits / 32
#define BMAX  2048

// -------- device scratch (no allocations allowed) --------
__device__ int      g_is64;
__device__ float    g_ce[BMAX];
__device__ int      g_corr[BMAX];
__device__ int      g_cnt[BMAX];
__device__ unsigned g_path[BMAX][NW];
__device__ float    g_bloss[BMAX];

// ---------------------------------------------------------------------------
// Kernel 0: detect labels dtype. Under int64, every odd 32-bit word (high half
// of a small nonnegative value) is 0. Under int32 random labels, essentially
// never. Scan a prefix of 2*SEQL words (safe under both interpretations).
// ---------------------------------------------------------------------------
__global__ void k_detect(const unsigned* __restrict__ lw)
{
    __shared__ unsigned r[256];
    unsigned acc = 0;
    for (int i = 2 * threadIdx.x + 1; i < 2 * SEQL; i += 512)
        acc |= lw[i];
    r[threadIdx.x] = acc;
    __syncthreads();
    for (int o = 128; o > 0; o >>= 1) {
        if (threadIdx.x < o) r[threadIdx.x] |= r[threadIdx.x + o];
        __syncthreads();
    }
    if (threadIdx.x == 0) g_is64 = (r[0] == 0u) ? 1 : 0;
}

// ---------------------------------------------------------------------------
// Kernel 1: per-batch CE sum, correct count, mask count, path bitmask.
// One block per batch row, thread-per-token, 8x float4 coalesced loads.
// ---------------------------------------------------------------------------
__global__ void __launch_bounds__(256) k_ce(const float* __restrict__ logits,
                                            const void*  __restrict__ labels)
{
    const int b   = blockIdx.x;
    const int tid = threadIdx.x;
    const int is64 = g_is64;

    __shared__ unsigned spath[NW];
    __shared__ float rf[256];
    __shared__ int   ra[256];
    __shared__ int   rb[256];

    for (int i = tid; i < NW; i += 256) spath[i] = 0u;
    __syncthreads();

    float ce_acc = 0.f;
    int corr = 0, cnt = 0;
    const float4* base = (const float4*)(logits + (size_t)b * SEQL * VOC);

    for (int s = tid; s < SEQL; s += 256) {
        // label first (independent load, overlaps logits latency)
        long long l = is64 ? ((const long long*)labels)[(size_t)b * SEQL + s]
                           : (long long)((const int*)labels)[(size_t)b * SEQL + s];
        const bool msk = (l != -100);
        const int  sl  = (l < 0) ? 0 : (int)l;

        const float4* p = base + (size_t)s * (VOC / 4);
        float xs[VOC];
        #pragma unroll
        for (int q = 0; q < VOC / 4; q++) {
            float4 v = __ldg(p + q);
            xs[4*q+0] = v.x; xs[4*q+1] = v.y; xs[4*q+2] = v.z; xs[4*q+3] = v.w;
        }
        // max / argmax (first-occurrence like jnp.argmax) + capture x[label]
        float m = xs[0]; int am = 0; float xl = xs[0];
        #pragma unroll
        for (int j = 1; j < VOC; j++) {
            if (xs[j] > m) { m = xs[j]; am = j; }
        }
        #pragma unroll
        for (int j = 0; j < VOC; j++) {
            if (j == sl) xl = xs[j];
        }
        float sum = 0.f;
        #pragma unroll
        for (int j = 0; j < VOC; j++) sum += __expf(xs[j] - m);

        if (msk) {
            ce_acc += m + __logf(sum) - xl;
            cnt++;
            if ((long long)am == l) corr++;
        }
        if (am == 6) atomicOr(&spath[s >> 5], 1u << (s & 31));
    }

    rf[tid] = ce_acc; ra[tid] = corr; rb[tid] = cnt;
    __syncthreads();
    for (int o = 128; o > 0; o >>= 1) {
        if (tid < o) { rf[tid] += rf[tid+o]; ra[tid] += ra[tid+o]; rb[tid] += rb[tid+o]; }
        __syncthreads();
    }
    if (tid == 0) { g_ce[b] = rf[0]; g_corr[b] = ra[0]; g_cnt[b] = rb[0]; }
    if (tid < NW) g_path[b][tid] = spath[tid];
}

// ---------------------------------------------------------------------------
// Kernel 2: per-batch spatial + connectivity penalties + per-batch total loss.
// One block per batch. Spatial: walk set bits of the 50-word mask, pairwise
// Manhattan distance to next set bit. Connectivity: min-label propagation with
// path compression in shared memory; components = #roots.
// ---------------------------------------------------------------------------
__global__ void __launch_bounds__(256) k_pen(const float* __restrict__ qh, int B)
{
    const int b   = blockIdx.x;
    const int tid = threadIdx.x;

    __shared__ unsigned sp[NW];
    __shared__ int lab[SEQL];
    __shared__ int chg;
    __shared__ float rf[256];
    __shared__ int   ri[256];

    for (int i = tid; i < NW; i += 256) sp[i] = g_path[b][i];
    __syncthreads();

    // ---- spatial penalty: successive path cells in flat order ----
    float spen = 0.f;
    if (tid < NW) {
        unsigned w = sp[tid];
        while (w) {
            int bit = __ffs(w) - 1;
            w &= w - 1;
            int i = tid * 32 + bit;
            int j = -1;
            if (w) {
                j = tid * 32 + __ffs(w) - 1;
            } else {
                for (int ww = tid + 1; ww < NW; ww++) {
                    unsigned v = sp[ww];
                    if (v) { j = ww * 32 + __ffs(v) - 1; break; }
                }
            }
            if (j >= 0) {
                int d = abs(i / GRIDW - j / GRIDW) + abs(i % GRIDW - j % GRIDW);
                if (d > 1) spen += (float)(d - 1) * 10.0f;
            }
        }
    }

    // ---- connectivity: CCL via min-label propagation + compression ----
    for (int i = tid; i < SEQL; i += 256)
        lab[i] = ((sp[i >> 5] >> (i & 31)) & 1u) ? i : SEQL;
    __syncthreads();

    for (;;) {
        if (tid == 0) chg = 0;
        __syncthreads();
        for (int i = tid; i < SEQL; i += 256) {
            int L = lab[i];
            if (L == SEQL) continue;
            int m = L;
            if (i >= GRIDW)            m = min(m, lab[i - GRIDW]);
            if (i <  SEQL - GRIDW)     m = min(m, lab[i + GRIDW]);
            int c = i % GRIDW;
            if (c > 0)                 m = min(m, lab[i - 1]);
            if (c < GRIDW - 1)         m = min(m, lab[i + 1]);
            if (m < L) { lab[i] = m; chg = 1; }
        }
        __syncthreads();
        if (!chg) break;
        // path compression (monotone decreasing; races are benign)
        for (int i = tid; i < SEQL; i += 256) {
            int L = lab[i];
            if (L < SEQL) lab[i] = lab[L];
        }
        __syncthreads();
    }

    int roots = 0;
    for (int i = tid; i < SEQL; i += 256)
        if (lab[i] == i) roots++;   // only masked cells can satisfy this

    rf[tid] = spen; ri[tid] = roots;
    __syncthreads();
    for (int o = 128; o > 0; o >>= 1) {
        if (tid < o) { rf[tid] += rf[tid+o]; ri[tid] += ri[tid+o]; }
        __syncthreads();
    }

    if (tid == 0) {
        int comp = ri[0];
        float conn = (comp > 1) ? (float)(comp - 1) * 5.0f : 0.f;
        int cnt = g_cnt[b];
        float divi = (float)max(cnt, 1);
        float lm = g_ce[b] / divi;
        float t = (g_corr[b] == cnt) ? 1.f : 0.f;   // 0==0 -> correct, matches ref
        float x = qh[b];
        float bce = fmaxf(x, 0.f) - x * t + log1pf(expf(-fabsf(x)));
        g_bloss[b] = lm + 0.5f * bce + (rf[0] + conn) / (float)B;
    }
}

// ---------------------------------------------------------------------------
// Kernel 3: final reduction over batches (double accum), write fp32 scalar.
// ---------------------------------------------------------------------------
__global__ void k_final(float* __restrict__ out, int B)
{
    __shared__ double rd[256];
    const int tid = threadIdx.x;
    double a = 0.0;
    for (int i = tid; i < B; i += 256) a += (double)g_bloss[i];
    rd[tid] = a;
    __syncthreads();
    for (int o = 128; o > 0; o >>= 1) {
        if (tid < o) rd[tid] += rd[tid + o];
        __syncthreads();
    }
    if (tid == 0) out[0] = (float)rd[0];
}

// ---------------------------------------------------------------------------
extern "C" void kernel_launch(void* const* d_in, const int* in_sizes, int n_in,
                              void* d_out, int out_size)
{
    const float* logits = (const float*)d_in[0];
    const void*  labels = d_in[1];
    const float* qh     = (const float*)d_in[2];
    // d_in[3] = halted, d_in[4] = steps: metrics-only in reference, unused.

    int B = in_sizes[2];           // q_halt_logits length
    if (B > BMAX) B = BMAX;        // dataset uses B=1024

    k_detect<<<1, 256>>>((const unsigned*)labels);
    k_ce<<<B, 256>>>(logits, labels);
    k_pen<<<B, 256>>>(qh, B);
    k_final<<<1, 256>>>((float*)d_out, B);
}